// round 5
// baseline (speedup 1.0000x reference)
#include <cuda_runtime.h>
#include <math.h>

#define BATCH 2
#define SEQ   2048
#define DIM   1024
#define HEADS 16
#define HDIM  64
#define MROWS (BATCH * SEQ)     /* 4096 */
#define NQKV  (3 * DIM)         /* 3072 */

// Scratch (device globals: no runtime allocation allowed)
__device__ float g_qkv[(size_t)MROWS * NQKV];   // ~50 MB
__device__ float g_att[(size_t)MROWS * DIM];    // ~17 MB

// ---------------------------------------------------------------------------
// helpers
// ---------------------------------------------------------------------------
__device__ __forceinline__ float tf32r(float x) {
    unsigned u;
    asm("cvt.rna.tf32.f32 %0, %1;" : "=r"(u) : "f"(x));
    return __uint_as_float(u);
}

__device__ __forceinline__ void mma_tf32(float c[4], const unsigned a[4], const unsigned b[2]) {
    asm volatile(
        "mma.sync.aligned.m16n8k8.row.col.f32.tf32.tf32.f32 "
        "{%0,%1,%2,%3}, {%4,%5,%6,%7}, {%8,%9}, {%0,%1,%2,%3};\n"
        : "+f"(c[0]), "+f"(c[1]), "+f"(c[2]), "+f"(c[3])
        : "r"(a[0]), "r"(a[1]), "r"(a[2]), "r"(a[3]), "r"(b[0]), "r"(b[1]));
}

// Fragment-ordered smem layouts.
// A (16x8 m16k8 block): 132 floats/block, addr = blk*132 + lane*4 + slot.
//   slot0=(grp,qid) slot1=(grp+8,qid) slot2=(grp,qid+4) slot3=(grp+8,qid+4)
//   -> one LDS.128 per A fragment.
// B (8x8 k8n8 block):   66 floats/block, addr = blk*66 + lane*2 + slot.
//   slot0=(k=qid,n=grp) slot1=(k=qid+4,n=grp)
//   -> one LDS.64 per B fragment.
#define ABLK 132
#define BBLK 66

// ---------------------------------------------------------------------------
// TF32 GEMM: C[M,N] = A[M,K] @ W[K,N] + bias[N]
// Block 128x128x32, 8 warps (2x4), warp tile 64x32, mma m16n8k8.
// Single-stage fragment-ordered smem, 2 CTAs/SM.
// ---------------------------------------------------------------------------
#define BM 128
#define BN 128
#define BK 32
#define A_NBLK (8 * 4)     /* bm 0..7, bk 0..3 : blk = bm*4+bk */
#define B_NBLK (16 * 4)    /* bn 0..15, bk 0..3 : blk = bn*4+bk */
#define GEMM_SMEM ((A_NBLK * ABLK + B_NBLK * BBLK) * (int)sizeof(float)) /* 33792B */

__global__ __launch_bounds__(256, 2) void gemm_tf32_kernel(
    const float* __restrict__ A, const float* __restrict__ W,
    const float* __restrict__ bias, float* __restrict__ C,
    int M, int N, int K)
{
    extern __shared__ float dyn[];
    float* As = dyn;                    // A_NBLK * ABLK
    float* Bs = dyn + A_NBLK * ABLK;    // B_NBLK * BBLK

    const int tid  = threadIdx.x;
    const int lane = tid & 31;
    const int warp = tid >> 5;
    const int wr   = warp >> 2;          // 0..1
    const int wc   = warp & 3;           // 0..3

    const int m0 = blockIdx.y * BM;
    const int n0 = blockIdx.x * BN;

    const int arow = tid >> 3;           // 0..31 (rows arow + 32*i)
    const int akc  = (tid & 7) * 4;      // k offset within BK (0,4,...,28)
    const int brow = tid >> 5;           // 0..7  (k rows brow + 8*i)
    const int bnc  = (tid & 31) * 4;     // n offset within BN

    // precomputed store bases
    // A: row -> bm=row>>4, grp_t=(row&15)&7, half=(row&15)>>3 ; col c=akc&7 fixed group
    const int a_bk   = akc >> 3;
    const int a_slotq = (akc & 4) ? 2 : 0;
    // B: k row -> bk, qid_t, slot ; n -> bn, grp_t
    const int b_bn   = bnc >> 3;
    const int b_g0   = bnc & 7;          // 0 or 4

    float acc[4][4][4];
#pragma unroll
    for (int mi = 0; mi < 4; ++mi)
#pragma unroll
        for (int nj = 0; nj < 4; ++nj)
#pragma unroll
            for (int r = 0; r < 4; ++r) acc[mi][nj][r] = 0.f;

    const int T = K / BK;

    for (int t = 0; t < T; ++t) {
        const int k0 = t * BK;
        // global loads (registers only)
        float4 va[4], vb[4];
#pragma unroll
        for (int i = 0; i < 4; ++i)
            va[i] = *(const float4*)(A + (size_t)(m0 + arow + 32 * i) * K + k0 + akc);
#pragma unroll
        for (int i = 0; i < 4; ++i)
            vb[i] = *(const float4*)(W + (size_t)(k0 + brow + 8 * i) * N + n0 + bnc);

        __syncthreads();   // previous compute done reading smem

        // store A fragments (cvt at store)
#pragma unroll
        for (int i = 0; i < 4; ++i) {
            const int row = arow + 32 * i;
            const int bm = row >> 4;
            const int r15 = row & 15;
            const int grp_t = r15 & 7;
            const int slot = a_slotq + (r15 >> 3);
            float* base = &As[(bm * 4 + a_bk) * ABLK + grp_t * 16 + slot];
            base[0]  = tf32r(va[i].x);
            base[4]  = tf32r(va[i].y);
            base[8]  = tf32r(va[i].z);
            base[12] = tf32r(va[i].w);
        }
        // store B fragments
#pragma unroll
        for (int i = 0; i < 4; ++i) {
            const int krow = brow + 8 * i;
            const int bk = krow >> 3;
            const int c = krow & 7;
            const int qid_t = c & 3;
            const int slot = c >> 2;
            float* base = &Bs[(b_bn * 4 + bk) * BBLK + (b_g0 * 4 + qid_t) * 2 + slot];
            base[0]  = tf32r(vb[i].x);   // grp_t = b_g0 + 0
            base[8]  = tf32r(vb[i].y);   // +1  (stride 4 lanes * 2)
            base[16] = tf32r(vb[i].z);
            base[24] = tf32r(vb[i].w);
        }
        __syncthreads();

        // compute: 4 k-steps of 8
#pragma unroll
        for (int ks = 0; ks < 4; ++ks) {
            uint4 af[4];
            uint2 bf[4];
#pragma unroll
            for (int mi = 0; mi < 4; ++mi)
                af[mi] = *(const uint4*)&As[((wr * 4 + mi) * 4 + ks) * ABLK + lane * 4];
#pragma unroll
            for (int nj = 0; nj < 4; ++nj)
                bf[nj] = *(const uint2*)&Bs[((wc * 4 + nj) * 4 + ks) * BBLK + lane * 2];
#pragma unroll
            for (int mi = 0; mi < 4; ++mi)
#pragma unroll
                for (int nj = 0; nj < 4; ++nj)
                    mma_tf32(acc[mi][nj], (const unsigned*)&af[mi], (const unsigned*)&bf[nj]);
        }
    }

    // epilogue: bias + store
    const int grp = lane >> 2;
    const int qid = lane & 3;
#pragma unroll
    for (int mi = 0; mi < 4; ++mi) {
#pragma unroll
        for (int nj = 0; nj < 4; ++nj) {
            const int row = m0 + wr * 64 + mi * 16 + grp;
            const int col = n0 + wc * 32 + nj * 8 + 2 * qid;
            const float b0 = bias[col];
            const float b1 = bias[col + 1];
            float2 v0 = make_float2(acc[mi][nj][0] + b0, acc[mi][nj][1] + b1);
            float2 v1 = make_float2(acc[mi][nj][2] + b0, acc[mi][nj][3] + b1);
            *(float2*)&C[(size_t)row * N + col] = v0;
            *(float2*)&C[(size_t)(row + 8) * N + col] = v1;
        }
    }
}

// ---------------------------------------------------------------------------
// Flash attention (causal), tf32, fragment-ordered K/V/P smem.
// Grid: (S/64, B*H), 128 threads (4 warps), 64-query tile, 16 q per warp.
// ---------------------------------------------------------------------------
#define QP 68
#define KV_NBLK (8 * 8)                 /* bn 0..7, bk 0..7 : blk = bn*8+bk */
#define PWARP (8 * ABLK)                /* 8 k-blocks per warp's 16x64 P */
#define FLASH_SMEM ((64 * QP + 2 * KV_NBLK * BBLK + 4 * PWARP) * (int)sizeof(float))

__global__ __launch_bounds__(128) void flash_tf32_kernel(
    const float* __restrict__ qkv, float* __restrict__ out)
{
    extern __shared__ float smf[];
    float* Qs = smf;                        // 64*QP (raw, one-time)
    float* Kp = Qs + 64 * QP;               // KV_NBLK*BBLK
    float* Vp = Kp + KV_NBLK * BBLK;        // KV_NBLK*BBLK
    float* Pp = Vp + KV_NBLK * BBLK;        // 4 * PWARP

    const int tid  = threadIdx.x;
    const int lane = tid & 31;
    const int warp = tid >> 5;     // 0..3, 16 queries each
    const int grp  = lane >> 2;
    const int qid  = lane & 3;

    const int bh = blockIdx.y;
    const int b  = bh / HEADS;
    const int h  = bh % HEADS;
    const int qt = gridDim.x - 1 - blockIdx.x;   // heavy tiles first
    const int q0 = qt * 64;
    const float scale = 0.125f;

    const float* qbase = qkv + (size_t)(b * SEQ) * NQKV + h * HDIM;
    const float* kbase = qbase + DIM;
    const float* vbase = qbase + 2 * DIM;

    const int lr = tid >> 4;            // 0..7
    const int lc = (tid & 15) * 4;      // 0..60

    // Load Q tile (tf32-rounded, raw layout; one-time)
#pragma unroll
    for (int i = 0; i < 8; ++i) {
        float4 v = *(const float4*)(qbase + (size_t)(q0 + lr + 8 * i) * NQKV + lc);
        *(float4*)&Qs[(lr + 8 * i) * QP + lc] =
            make_float4(tf32r(v.x), tf32r(v.y), tf32r(v.z), tf32r(v.w));
    }
    __syncthreads();

    // Q fragments, register-resident for whole kernel
    unsigned qf[8][4];
#pragma unroll
    for (int ks = 0; ks < 8; ++ks) {
        const float* base = &Qs[(warp * 16 + grp) * QP + ks * 8 + qid];
        qf[ks][0] = __float_as_uint(base[0]);
        qf[ks][1] = __float_as_uint(base[8 * QP]);
        qf[ks][2] = __float_as_uint(base[4]);
        qf[ks][3] = __float_as_uint(base[8 * QP + 4]);
    }

    float m0r = -INFINITY, m1r = -INFINITY, l0 = 0.f, l1 = 0.f;
    float o[8][4];
#pragma unroll
    for (int j = 0; j < 8; ++j)
#pragma unroll
        for (int r = 0; r < 4; ++r) o[j][r] = 0.f;

    // K store indices (B-layout: n=kv row, k=d):
    const int k_bkd  = lc >> 3;           // bk from d
    const int k_slot = (lc & 4) ? 1 : 0;  // slot from d (c>>2)
    // V store indices (B-layout: n=d, k=kv):
    const int v_bnd  = lc >> 3;           // bn from d
    const int v_g0   = lc & 7;            // grp_t base from d (0 or 4)

    const int ntiles = qt + 1;
    for (int t = 0; t < ntiles; ++t) {
        const int k0 = t * 64;
        // global loads first (regs only)
        float4 kv4[8], vv4[8];
#pragma unroll
        for (int i = 0; i < 8; ++i) {
            const int row = lr + 8 * i;
            kv4[i] = *(const float4*)(kbase + (size_t)(k0 + row) * NQKV + lc);
            vv4[i] = *(const float4*)(vbase + (size_t)(k0 + row) * NQKV + lc);
        }
        __syncthreads();
        // store K fragments
#pragma unroll
        for (int i = 0; i < 8; ++i) {
            const int kvr = lr + 8 * i;        // kv row index
            const int bn = kvr >> 3;
            const int gk = kvr & 7;
            float* base = &Kp[(bn * 8 + k_bkd) * BBLK + gk * 8 + k_slot];
            base[0] = tf32r(kv4[i].x);         // qid_t = 0..3, stride 2
            base[2] = tf32r(kv4[i].y);
            base[4] = tf32r(kv4[i].z);
            base[6] = tf32r(kv4[i].w);
        }
        // store V fragments
#pragma unroll
        for (int i = 0; i < 8; ++i) {
            const int kvr = lr + 8 * i;
            const int bk = kvr >> 3;
            const int c = kvr & 7;
            const int qv = c & 3;
            const int sv = c >> 2;
            float* base = &Vp[(v_bnd * 8 + bk) * BBLK + (v_g0 * 4 + qv) * 2 + sv];
            base[0]  = tf32r(vv4[i].x);        // grp_t = v_g0 + 0..3, stride 8
            base[8]  = tf32r(vv4[i].y);
            base[16] = tf32r(vv4[i].z);
            base[24] = tf32r(vv4[i].w);
        }
        __syncthreads();

        // S = Q K^T  (warp tile 16x64)
        float s[8][4];
#pragma unroll
        for (int j = 0; j < 8; ++j) {
            s[j][0] = s[j][1] = s[j][2] = s[j][3] = 0.f;
#pragma unroll
            for (int ks = 0; ks < 8; ++ks) {
                uint2 bf = *(const uint2*)&Kp[(j * 8 + ks) * BBLK + lane * 2];
                mma_tf32(s[j], qf[ks], (const unsigned*)&bf);
            }
        }

        // scale + causal mask (diag tile only)
        const bool diag = (t == ntiles - 1);
        const int qi0 = q0 + warp * 16 + grp;
#pragma unroll
        for (int j = 0; j < 8; ++j) {
#pragma unroll
            for (int r = 0; r < 4; ++r) {
                float v = s[j][r] * scale;
                if (diag) {
                    const int kj = k0 + j * 8 + 2 * qid + (r & 1);
                    const int qi = qi0 + ((r >= 2) ? 8 : 0);
                    if (kj > qi) v = -INFINITY;
                }
                s[j][r] = v;
            }
        }

        // online softmax (rows grp and grp+8)
        float mx0 = -INFINITY, mx1 = -INFINITY;
#pragma unroll
        for (int j = 0; j < 8; ++j) {
            mx0 = fmaxf(mx0, fmaxf(s[j][0], s[j][1]));
            mx1 = fmaxf(mx1, fmaxf(s[j][2], s[j][3]));
        }
        mx0 = fmaxf(mx0, __shfl_xor_sync(0xffffffffu, mx0, 1));
        mx0 = fmaxf(mx0, __shfl_xor_sync(0xffffffffu, mx0, 2));
        mx1 = fmaxf(mx1, __shfl_xor_sync(0xffffffffu, mx1, 1));
        mx1 = fmaxf(mx1, __shfl_xor_sync(0xffffffffu, mx1, 2));

        const float nm0 = fmaxf(m0r, mx0);
        const float nm1 = fmaxf(m1r, mx1);
        const float corr0 = __expf(m0r - nm0);
        const float corr1 = __expf(m1r - nm1);
        m0r = nm0; m1r = nm1;

        float sum0 = 0.f, sum1 = 0.f;
#pragma unroll
        for (int j = 0; j < 8; ++j) {
            s[j][0] = __expf(s[j][0] - nm0);
            s[j][1] = __expf(s[j][1] - nm0);
            s[j][2] = __expf(s[j][2] - nm1);
            s[j][3] = __expf(s[j][3] - nm1);
            sum0 += s[j][0] + s[j][1];
            sum1 += s[j][2] + s[j][3];
        }
        sum0 += __shfl_xor_sync(0xffffffffu, sum0, 1);
        sum0 += __shfl_xor_sync(0xffffffffu, sum0, 2);
        sum1 += __shfl_xor_sync(0xffffffffu, sum1, 1);
        sum1 += __shfl_xor_sync(0xffffffffu, sum1, 2);
        l0 = l0 * corr0 + sum0;
        l1 = l1 * corr1 + sum1;
#pragma unroll
        for (int j = 0; j < 8; ++j) {
            o[j][0] *= corr0; o[j][1] *= corr0;
            o[j][2] *= corr1; o[j][3] *= corr1;
        }

        // P: write C-frags directly in A-fragment order (warp-private region)
        {
            float* wb = &Pp[warp * PWARP];
            const int c0 = 2 * qid;
            const int s_off = (qid < 2) ? 0 : 2;
            const int lane0 = grp * 4 + (c0 & 3);
            const int lane1 = grp * 4 + ((c0 + 1) & 3);
#pragma unroll
            for (int j = 0; j < 8; ++j) {
                *(float2*)&wb[j * ABLK + lane0 * 4 + s_off] =
                    make_float2(tf32r(s[j][0]), tf32r(s[j][2]));
                *(float2*)&wb[j * ABLK + lane1 * 4 + s_off] =
                    make_float2(tf32r(s[j][1]), tf32r(s[j][3]));
            }
        }
        __syncwarp();

        // O += P @ V
        {
            const float* wb = &Pp[warp * PWARP];
#pragma unroll
            for (int ks = 0; ks < 8; ++ks) {
                uint4 pf = *(const uint4*)&wb[ks * ABLK + lane * 4];
#pragma unroll
                for (int j = 0; j < 8; ++j) {
                    uint2 bf = *(const uint2*)&Vp[(j * 8 + ks) * BBLK + lane * 2];
                    mma_tf32(o[j], (const unsigned*)&pf, (const unsigned*)&bf);
                }
            }
        }
    }

    // write normalized output
    const float inv0 = 1.0f / l0;
    const float inv1 = 1.0f / l1;
    const int row0 = q0 + warp * 16 + grp;
#pragma unroll
    for (int j = 0; j < 8; ++j) {
        const int col = h * HDIM + j * 8 + 2 * qid;
        *(float2*)&out[((size_t)(b * SEQ) + row0) * DIM + col] =
            make_float2(o[j][0] * inv0, o[j][1] * inv0);
        *(float2*)&out[((size_t)(b * SEQ) + row0 + 8) * DIM + col] =
            make_float2(o[j][2] * inv1, o[j][3] * inv1);
    }
}

// ---------------------------------------------------------------------------
extern "C" void kernel_launch(void* const* d_in, const int* in_sizes, int n_in,
                              void* d_out, int out_size)
{
    const float* x      = (const float*)d_in[0];   // [B,S,D]
    const float* qkv_w  = (const float*)d_in[1];   // [D, 3D]
    const float* qkv_b  = (const float*)d_in[2];   // [3D]
    const float* out_w  = (const float*)d_in[3];   // [D, D]
    const float* out_b  = (const float*)d_in[4];   // [D]
    float* out = (float*)d_out;

    float* qkv_buf = nullptr;
    float* att_buf = nullptr;
    cudaGetSymbolAddress((void**)&qkv_buf, g_qkv);
    cudaGetSymbolAddress((void**)&att_buf, g_att);

    cudaFuncSetAttribute(gemm_tf32_kernel,
                         cudaFuncAttributeMaxDynamicSharedMemorySize, GEMM_SMEM);
    cudaFuncSetAttribute(flash_tf32_kernel,
                         cudaFuncAttributeMaxDynamicSharedMemorySize, FLASH_SMEM);

    // 1) QKV projection: [4096,1024] @ [1024,3072] + b
    {
        dim3 grid(NQKV / BN, MROWS / BM);
        gemm_tf32_kernel<<<grid, 256, GEMM_SMEM>>>(x, qkv_w, qkv_b, qkv_buf,
                                                   MROWS, NQKV, DIM);
    }
    // 2) Causal flash attention (tf32 tensor cores)
    {
        dim3 grid(SEQ / 64, BATCH * HEADS);
        flash_tf32_kernel<<<grid, 128, FLASH_SMEM>>>(qkv_buf, att_buf);
    }
    // 3) Output projection: [4096,1024] @ [1024,1024] + b
    {
        dim3 grid(DIM / BN, MROWS / BM);
        gemm_tf32_kernel<<<grid, 256, GEMM_SMEM>>>(att_buf, out_w, out_b, out,
                                                   MROWS, DIM, DIM);
    }
}

// round 11
// speedup vs baseline: 2.1518x; 2.1518x over previous
#include <cuda_runtime.h>
#include <math.h>

#define BATCH 2
#define SEQ   2048
#define DIM   1024
#define HEADS 16
#define HDIM  64
#define MROWS (BATCH * SEQ)     /* 4096 */
#define NQKV  (3 * DIM)         /* 3072 */

// Scratch (device globals: no runtime allocation allowed).
// Kept under ~85MB total: g_att doubles as the rounded-x buffer (xr is dead
// before flash writes att), and both rounded weight matrices share g_wrs.
__device__ float g_qkv[(size_t)MROWS * NQKV];                 // 50.3 MB
__device__ float g_att[(size_t)MROWS * DIM];                  // 16.8 MB (xr alias, then att)
__device__ float g_wrs[(size_t)DIM * NQKV + (size_t)DIM * DIM]; // 16.8 MB (wr | owr)

// ---------------------------------------------------------------------------
// helpers
// ---------------------------------------------------------------------------
__device__ __forceinline__ float tf32r(float x) {
    unsigned u;
    asm("cvt.rna.tf32.f32 %0, %1;" : "=r"(u) : "f"(x));
    return __uint_as_float(u);
}

__device__ __forceinline__ void mma_tf32(float c[4], const unsigned a[4], const unsigned b[2]) {
    asm volatile(
        "mma.sync.aligned.m16n8k8.row.col.f32.tf32.tf32.f32 "
        "{%0,%1,%2,%3}, {%4,%5,%6,%7}, {%8,%9}, {%0,%1,%2,%3};\n"
        : "+f"(c[0]), "+f"(c[1]), "+f"(c[2]), "+f"(c[3])
        : "r"(a[0]), "r"(a[1]), "r"(a[2]), "r"(a[3]), "r"(b[0]), "r"(b[1]));
}

__device__ __forceinline__ void cp16(float* s, const float* g) {
    unsigned sa = (unsigned)__cvta_generic_to_shared(s);
    asm volatile("cp.async.cg.shared.global [%0], [%1], 16;\n" :: "r"(sa), "l"(g));
}
#define CP_COMMIT() asm volatile("cp.async.commit_group;\n" ::: "memory")
#define CP_WAIT(N)  asm volatile("cp.async.wait_group %0;\n" :: "n"(N) : "memory")

// ---------------------------------------------------------------------------
// Elementwise tf32 pre-round: dst[i] = round_tf32(src[i])
// ---------------------------------------------------------------------------
__global__ __launch_bounds__(256) void round_tf32_kernel(
    const float* __restrict__ src, float* __restrict__ dst, int n4)
{
    const int i = (blockIdx.x * 256 + threadIdx.x);
    if (i < n4) {
        float4 v = ((const float4*)src)[i];
        ((float4*)dst)[i] = make_float4(tf32r(v.x), tf32r(v.y), tf32r(v.z), tf32r(v.w));
    }
}

// ---------------------------------------------------------------------------
// TF32 GEMM: C[M,N] = A[M,K] @ W[K,N] + bias[N]   (A, W pre-rounded to tf32)
// Block 128x128x32, 8 warps (2x4), warp tile 64x32, mma m16n8k8.
// 2-stage cp.async ring, 2 CTAs/SM, one barrier per K-iter.
// ---------------------------------------------------------------------------
#define BM 128
#define BN 128
#define BK 32
#define APITCH 36    /* conflict-free A-frag loads */
#define BPITCH 132   /* conflict-free B-frag loads */
#define ASZ (BM * APITCH)
#define BSZ (BK * BPITCH)
#define GEMM_SMEM ((2 * (ASZ + BSZ)) * (int)sizeof(float))   /* 70656 B */

template <bool ROUND_OUT>
__global__ __launch_bounds__(256, 2) void gemm_tf32_kernel(
    const float* __restrict__ A, const float* __restrict__ W,
    const float* __restrict__ bias, float* __restrict__ C,
    int M, int N, int K)
{
    extern __shared__ float dyn[];
    float* As = dyn;               // [2][BM][APITCH]
    float* Bs = dyn + 2 * ASZ;     // [2][BK][BPITCH]

    const int tid  = threadIdx.x;
    const int lane = tid & 31;
    const int warp = tid >> 5;
    const int wr   = warp >> 2;          // 0..1
    const int wc   = warp & 3;           // 0..3
    const int grp  = lane >> 2;          // 0..7
    const int qid  = lane & 3;           // 0..3

    const int m0 = blockIdx.y * BM;
    const int n0 = blockIdx.x * BN;

    const int arow = tid >> 3;           // 0..31 (rows arow + 32*i)
    const int akc  = (tid & 7) * 4;      // k offset within BK
    const int brow = tid >> 5;           // 0..7  (rows brow + 8*i)
    const int bnc  = (tid & 31) * 4;     // n offset within BN

    const int T = K / BK;

    auto loadtile = [&](int t) {
        float* as = As + (t & 1) * ASZ;
        float* bs = Bs + (t & 1) * BSZ;
        const int k0 = t * BK;
#pragma unroll
        for (int i = 0; i < 4; ++i)
            cp16(&as[(arow + 32 * i) * APITCH + akc],
                 A + (size_t)(m0 + arow + 32 * i) * K + k0 + akc);
#pragma unroll
        for (int i = 0; i < 4; ++i)
            cp16(&bs[(brow + 8 * i) * BPITCH + bnc],
                 W + (size_t)(k0 + brow + 8 * i) * N + n0 + bnc);
        CP_COMMIT();
    };

    float acc[4][4][4];
#pragma unroll
    for (int mi = 0; mi < 4; ++mi)
#pragma unroll
        for (int nj = 0; nj < 4; ++nj)
#pragma unroll
            for (int r = 0; r < 4; ++r) acc[mi][nj][r] = 0.f;

    loadtile(0);

    for (int t = 0; t < T; ++t) {
        CP_WAIT(0);              // tile t resident (this thread)
        __syncthreads();         // visible to all; all warps done with stage t^1
        if (t + 1 < T) loadtile(t + 1);

        const float* as = As + (t & 1) * ASZ;
        const float* bs = Bs + (t & 1) * BSZ;

#pragma unroll
        for (int ks = 0; ks < 4; ++ks) {
            unsigned af[4][4], bf[4][2];
#pragma unroll
            for (int mi = 0; mi < 4; ++mi) {
                const float* base = &as[(wr * 64 + mi * 16 + grp) * APITCH + ks * 8 + qid];
                af[mi][0] = __float_as_uint(base[0]);
                af[mi][1] = __float_as_uint(base[8 * APITCH]);
                af[mi][2] = __float_as_uint(base[4]);
                af[mi][3] = __float_as_uint(base[8 * APITCH + 4]);
            }
#pragma unroll
            for (int nj = 0; nj < 4; ++nj) {
                const float* base = &bs[(ks * 8 + qid) * BPITCH + wc * 32 + nj * 8 + grp];
                bf[nj][0] = __float_as_uint(base[0]);
                bf[nj][1] = __float_as_uint(base[4 * BPITCH]);
            }
#pragma unroll
            for (int mi = 0; mi < 4; ++mi)
#pragma unroll
                for (int nj = 0; nj < 4; ++nj)
                    mma_tf32(acc[mi][nj], af[mi], bf[nj]);
        }
    }

    // epilogue: bias + store (optionally tf32-rounded for downstream MMA use)
#pragma unroll
    for (int mi = 0; mi < 4; ++mi) {
#pragma unroll
        for (int nj = 0; nj < 4; ++nj) {
            const int row = m0 + wr * 64 + mi * 16 + grp;
            const int col = n0 + wc * 32 + nj * 8 + 2 * qid;
            const float b0 = bias[col];
            const float b1 = bias[col + 1];
            float c00 = acc[mi][nj][0] + b0, c01 = acc[mi][nj][1] + b1;
            float c10 = acc[mi][nj][2] + b0, c11 = acc[mi][nj][3] + b1;
            if (ROUND_OUT) {
                c00 = tf32r(c00); c01 = tf32r(c01);
                c10 = tf32r(c10); c11 = tf32r(c11);
            }
            *(float2*)&C[(size_t)row * N + col] = make_float2(c00, c01);
            *(float2*)&C[(size_t)(row + 8) * N + col] = make_float2(c10, c11);
        }
    }
}

// ---------------------------------------------------------------------------
// Flash attention (causal), tf32 tensor-core. qkv pre-rounded; no in-loop cvt
// except P. 69KB smem, 3 CTAs/SM. Grid: (S/64, B*H), 128 threads (4 warps).
// ---------------------------------------------------------------------------
#define QP 68   /* pitch for Qs/Ks/Ps: conflict-free frag loads */
#define VP 72   /* pitch for Vs */
#define FLASH_SMEM ((3 * 64 * QP + 64 * VP) * (int)sizeof(float))  /* 70656 B */

__global__ __launch_bounds__(128) void flash_tf32_kernel(
    const float* __restrict__ qkv, float* __restrict__ out)
{
    extern __shared__ float smf[];
    float* Qs = smf;               // 64*QP
    float* Ks = Qs + 64 * QP;      // 64*QP
    float* Ps = Ks + 64 * QP;      // 64*QP
    float* Vs = Ps + 64 * QP;      // 64*VP

    const int tid  = threadIdx.x;
    const int lane = tid & 31;
    const int warp = tid >> 5;     // 0..3, 16 queries each
    const int grp  = lane >> 2;
    const int qid  = lane & 3;

    const int bh = blockIdx.y;
    const int b  = bh / HEADS;
    const int h  = bh % HEADS;
    const int qt = gridDim.x - 1 - blockIdx.x;   // heavy tiles first
    const int q0 = qt * 64;
    const float scale = 0.125f;

    const float* qbase = qkv + (size_t)(b * SEQ) * NQKV + h * HDIM;
    const float* kbase = qbase + DIM;
    const float* vbase = qbase + 2 * DIM;

    const int lr = tid >> 4;            // 0..7
    const int lc = (tid & 15) * 4;      // 0..60

    // Load Q tile (already tf32-rounded in gmem)
#pragma unroll
    for (int i = 0; i < 8; ++i) {
        float4 v = *(const float4*)(qbase + (size_t)(q0 + lr + 8 * i) * NQKV + lc);
        *(float4*)&Qs[(lr + 8 * i) * QP + lc] = v;
    }
    __syncthreads();

    // Q fragments, register-resident for whole kernel
    unsigned qf[8][4];
#pragma unroll
    for (int ks = 0; ks < 8; ++ks) {
        const float* base = &Qs[(warp * 16 + grp) * QP + ks * 8 + qid];
        qf[ks][0] = __float_as_uint(base[0]);
        qf[ks][1] = __float_as_uint(base[8 * QP]);
        qf[ks][2] = __float_as_uint(base[4]);
        qf[ks][3] = __float_as_uint(base[8 * QP + 4]);
    }

    float m0r = -INFINITY, m1r = -INFINITY, l0 = 0.f, l1 = 0.f;
    float o[8][4];
#pragma unroll
    for (int j = 0; j < 8; ++j)
#pragma unroll
        for (int r = 0; r < 4; ++r) o[j][r] = 0.f;

    const int ntiles = qt + 1;
    for (int t = 0; t < ntiles; ++t) {
        const int k0 = t * 64;
        __syncthreads();
        // Load K,V tiles (already rounded; raw vectorized copy)
#pragma unroll
        for (int i = 0; i < 8; ++i) {
            const int row = lr + 8 * i;
            float4 kv = *(const float4*)(kbase + (size_t)(k0 + row) * NQKV + lc);
            float4 vv = *(const float4*)(vbase + (size_t)(k0 + row) * NQKV + lc);
            *(float4*)&Ks[row * QP + lc] = kv;
            *(float4*)&Vs[row * VP + lc] = vv;
        }
        __syncthreads();

        // S = Q K^T  (warp tile 16x64)
        float s[8][4];
#pragma unroll
        for (int j = 0; j < 8; ++j) {
            s[j][0] = s[j][1] = s[j][2] = s[j][3] = 0.f;
#pragma unroll
            for (int ks = 0; ks < 8; ++ks) {
                const float* base = &Ks[(j * 8 + grp) * QP + ks * 8 + qid];
                unsigned bf[2];
                bf[0] = __float_as_uint(base[0]);
                bf[1] = __float_as_uint(base[4]);
                mma_tf32(s[j], qf[ks], bf);
            }
        }

        // scale + causal mask (diag tile only)
        const bool diag = (t == ntiles - 1);
        const int qi0 = q0 + warp * 16 + grp;
#pragma unroll
        for (int j = 0; j < 8; ++j) {
#pragma unroll
            for (int r = 0; r < 4; ++r) {
                float v = s[j][r] * scale;
                if (diag) {
                    const int kj = k0 + j * 8 + 2 * qid + (r & 1);
                    const int qi = qi0 + ((r >= 2) ? 8 : 0);
                    if (kj > qi) v = -INFINITY;
                }
                s[j][r] = v;
            }
        }

        // online softmax (rows grp and grp+8; 4-lane groups share a row)
        float mx0 = -INFINITY, mx1 = -INFINITY;
#pragma unroll
        for (int j = 0; j < 8; ++j) {
            mx0 = fmaxf(mx0, fmaxf(s[j][0], s[j][1]));
            mx1 = fmaxf(mx1, fmaxf(s[j][2], s[j][3]));
        }
        mx0 = fmaxf(mx0, __shfl_xor_sync(0xffffffffu, mx0, 1));
        mx0 = fmaxf(mx0, __shfl_xor_sync(0xffffffffu, mx0, 2));
        mx1 = fmaxf(mx1, __shfl_xor_sync(0xffffffffu, mx1, 1));
        mx1 = fmaxf(mx1, __shfl_xor_sync(0xffffffffu, mx1, 2));

        const float nm0 = fmaxf(m0r, mx0);
        const float nm1 = fmaxf(m1r, mx1);
        const float corr0 = __expf(m0r - nm0);
        const float corr1 = __expf(m1r - nm1);
        m0r = nm0; m1r = nm1;

        float sum0 = 0.f, sum1 = 0.f;
#pragma unroll
        for (int j = 0; j < 8; ++j) {
            s[j][0] = __expf(s[j][0] - nm0);
            s[j][1] = __expf(s[j][1] - nm0);
            s[j][2] = __expf(s[j][2] - nm1);
            s[j][3] = __expf(s[j][3] - nm1);
            sum0 += s[j][0] + s[j][1];
            sum1 += s[j][2] + s[j][3];
        }
        sum0 += __shfl_xor_sync(0xffffffffu, sum0, 1);
        sum0 += __shfl_xor_sync(0xffffffffu, sum0, 2);
        sum1 += __shfl_xor_sync(0xffffffffu, sum1, 1);
        sum1 += __shfl_xor_sync(0xffffffffu, sum1, 2);
        l0 = l0 * corr0 + sum0;
        l1 = l1 * corr1 + sum1;
#pragma unroll
        for (int j = 0; j < 8; ++j) {
            o[j][0] *= corr0; o[j][1] *= corr0;
            o[j][2] *= corr1; o[j][3] *= corr1;
        }

        // P fragments -> smem (C-layout -> A-layout round trip), warp-private
#pragma unroll
        for (int j = 0; j < 8; ++j) {
            float* p0 = &Ps[(warp * 16 + grp) * QP + j * 8 + 2 * qid];
            float* p1 = &Ps[(warp * 16 + grp + 8) * QP + j * 8 + 2 * qid];
            *(float2*)p0 = make_float2(tf32r(s[j][0]), tf32r(s[j][1]));
            *(float2*)p1 = make_float2(tf32r(s[j][2]), tf32r(s[j][3]));
        }
        __syncwarp();

        // O += P @ V
#pragma unroll
        for (int ks = 0; ks < 8; ++ks) {
            const float* abase = &Ps[(warp * 16 + grp) * QP + ks * 8 + qid];
            unsigned pf[4];
            pf[0] = __float_as_uint(abase[0]);
            pf[1] = __float_as_uint(abase[8 * QP]);
            pf[2] = __float_as_uint(abase[4]);
            pf[3] = __float_as_uint(abase[8 * QP + 4]);
#pragma unroll
            for (int j = 0; j < 8; ++j) {
                const float* bbase = &Vs[(ks * 8 + qid) * VP + j * 8 + grp];
                unsigned bf[2];
                bf[0] = __float_as_uint(bbase[0]);
                bf[1] = __float_as_uint(bbase[4 * VP]);
                mma_tf32(o[j], pf, bf);
            }
        }
    }

    // write normalized output (tf32-rounded: feeds out-proj MMA directly)
    const float inv0 = 1.0f / l0;
    const float inv1 = 1.0f / l1;
    const int row0 = q0 + warp * 16 + grp;
#pragma unroll
    for (int j = 0; j < 8; ++j) {
        const int col = h * HDIM + j * 8 + 2 * qid;
        *(float2*)&out[((size_t)(b * SEQ) + row0) * DIM + col] =
            make_float2(tf32r(o[j][0] * inv0), tf32r(o[j][1] * inv0));
        *(float2*)&out[((size_t)(b * SEQ) + row0 + 8) * DIM + col] =
            make_float2(tf32r(o[j][2] * inv1), tf32r(o[j][3] * inv1));
    }
}

// ---------------------------------------------------------------------------
extern "C" void kernel_launch(void* const* d_in, const int* in_sizes, int n_in,
                              void* d_out, int out_size)
{
    const float* x      = (const float*)d_in[0];   // [B,S,D]
    const float* qkv_w  = (const float*)d_in[1];   // [D, 3D]
    const float* qkv_b  = (const float*)d_in[2];   // [3D]
    const float* out_w  = (const float*)d_in[3];   // [D, D]
    const float* out_b  = (const float*)d_in[4];   // [D]
    float* out = (float*)d_out;

    float *qkv_buf, *att_buf, *wrs;
    cudaGetSymbolAddress((void**)&qkv_buf, g_qkv);
    cudaGetSymbolAddress((void**)&att_buf, g_att);
    cudaGetSymbolAddress((void**)&wrs, g_wrs);

    // Buffer plan (stream-ordered, safe aliasing):
    //   xr  = att_buf          (rounded x; dead after QKV GEMM, before flash writes att)
    //   wr  = wrs              (rounded qkv_w)
    //   owr = wrs + DIM*NQKV   (rounded out_w)
    float* xr  = att_buf;
    float* wr  = wrs;
    float* owr = wrs + (size_t)DIM * NQKV;

    cudaFuncSetAttribute(gemm_tf32_kernel<true>,
                         cudaFuncAttributeMaxDynamicSharedMemorySize, GEMM_SMEM);
    cudaFuncSetAttribute(gemm_tf32_kernel<false>,
                         cudaFuncAttributeMaxDynamicSharedMemorySize, GEMM_SMEM);
    cudaFuncSetAttribute(flash_tf32_kernel,
                         cudaFuncAttributeMaxDynamicSharedMemorySize, FLASH_SMEM);

    // 0) pre-round inputs to tf32
    {
        int n4;
        n4 = MROWS * DIM / 4;
        round_tf32_kernel<<<(n4 + 255) / 256, 256>>>(x, xr, n4);
        n4 = DIM * NQKV / 4;
        round_tf32_kernel<<<(n4 + 255) / 256, 256>>>(qkv_w, wr, n4);
        n4 = DIM * DIM / 4;
        round_tf32_kernel<<<(n4 + 255) / 256, 256>>>(out_w, owr, n4);
    }
    // 1) QKV projection: [4096,1024] @ [1024,3072] + b  (rounded output)
    {
        dim3 grid(NQKV / BN, MROWS / BM);
        gemm_tf32_kernel<true><<<grid, 256, GEMM_SMEM>>>(xr, wr, qkv_b, qkv_buf,
                                                         MROWS, NQKV, DIM);
    }
    // 2) Causal flash attention (tf32 tensor cores); overwrites xr with att
    {
        dim3 grid(SEQ / 64, BATCH * HEADS);
        flash_tf32_kernel<<<grid, 128, FLASH_SMEM>>>(qkv_buf, att_buf);
    }
    // 3) Output projection: [4096,1024] @ [1024,1024] + b  (exact fp32 out)
    {
        dim3 grid(DIM / BN, MROWS / BM);
        gemm_tf32_kernel<false><<<grid, 256, GEMM_SMEM>>>(att_buf, owr, out_b, out,
                                                          MROWS, DIM, DIM);
    }
}

// round 12
// speedup vs baseline: 2.3097x; 1.0734x over previous
#include <cuda_runtime.h>
#include <math.h>

#define BATCH 2
#define SEQ   2048
#define DIM   1024
#define HEADS 16
#define HDIM  64
#define MROWS (BATCH * SEQ)     /* 4096 */
#define NQKV  (3 * DIM)         /* 3072 */

// Scratch (device globals; keep total ~84MB — larger static footprints have
// correlated with broker container failures).
__device__ float g_qkv[(size_t)MROWS * NQKV];                   // 50.3 MB
__device__ float g_att[(size_t)MROWS * DIM];                    // 16.8 MB (xr alias, then att)
__device__ float g_wrs[(size_t)DIM * NQKV + (size_t)DIM * DIM]; // 16.8 MB (wr_t | owr_t)

// ---------------------------------------------------------------------------
// helpers
// ---------------------------------------------------------------------------
__device__ __forceinline__ float tf32r(float x) {
    unsigned u;
    asm("cvt.rna.tf32.f32 %0, %1;" : "=r"(u) : "f"(x));
    return __uint_as_float(u);
}

__device__ __forceinline__ void mma_tf32(float c[4], const unsigned a[4], const unsigned b[2]) {
    asm volatile(
        "mma.sync.aligned.m16n8k8.row.col.f32.tf32.tf32.f32 "
        "{%0,%1,%2,%3}, {%4,%5,%6,%7}, {%8,%9}, {%0,%1,%2,%3};\n"
        : "+f"(c[0]), "+f"(c[1]), "+f"(c[2]), "+f"(c[3])
        : "r"(a[0]), "r"(a[1]), "r"(a[2]), "r"(a[3]), "r"(b[0]), "r"(b[1]));
}

// ldmatrix: tf32 fragments via b16 8x8 matrices (each = one 8x4 tf32 block).
__device__ __forceinline__ void ldsm_x4(unsigned r[4], const float* p) {
    unsigned a = (unsigned)__cvta_generic_to_shared(p);
    asm volatile("ldmatrix.sync.aligned.m8n8.x4.shared.b16 {%0,%1,%2,%3}, [%4];"
                 : "=r"(r[0]), "=r"(r[1]), "=r"(r[2]), "=r"(r[3]) : "r"(a));
}

__device__ __forceinline__ void cp16(float* s, const float* g) {
    unsigned sa = (unsigned)__cvta_generic_to_shared(s);
    asm volatile("cp.async.cg.shared.global [%0], [%1], 16;\n" :: "r"(sa), "l"(g));
}
#define CP_COMMIT() asm volatile("cp.async.commit_group;\n" ::: "memory")
#define CP_WAIT(N)  asm volatile("cp.async.wait_group %0;\n" :: "n"(N) : "memory")

// ---------------------------------------------------------------------------
// Prep kernels
// ---------------------------------------------------------------------------
__global__ __launch_bounds__(256) void round_tf32_kernel(
    const float* __restrict__ src, float* __restrict__ dst, int n4)
{
    const int i = (blockIdx.x * 256 + threadIdx.x);
    if (i < n4) {
        float4 v = ((const float4*)src)[i];
        ((float4*)dst)[i] = make_float4(tf32r(v.x), tf32r(v.y), tf32r(v.z), tf32r(v.w));
    }
}

// dst[n][k] = round(src[k][n]);  src is [K][N]. 32x32 smem tiles, 256 threads.
__global__ __launch_bounds__(256) void round_transpose_kernel(
    const float* __restrict__ src, float* __restrict__ dst, int K, int N)
{
    __shared__ float t[32][33];
    const int n0 = blockIdx.x * 32;
    const int k0 = blockIdx.y * 32;
    const int tx = threadIdx.x & 31;
    const int ty = threadIdx.x >> 5;       // 0..7
#pragma unroll
    for (int i = 0; i < 32; i += 8)
        t[ty + i][tx] = src[(size_t)(k0 + ty + i) * N + n0 + tx];
    __syncthreads();
#pragma unroll
    for (int i = 0; i < 32; i += 8)
        dst[(size_t)(n0 + ty + i) * K + k0 + tx] = tf32r(t[tx][ty + i]);
}

// ---------------------------------------------------------------------------
// TF32 GEMM: C[M,N] = A[M,K] @ Wt[N,K]^T + bias[N]   (A, Wt pre-rounded)
// Block 128x128x32, 8 warps (2x4), warp tile 64x32, mma m16n8k8.
// Both smem tiles are [128 rows][32 k] pitch 36; all fragment loads via LDSM.
// 2-stage cp.async ring, 2 CTAs/SM.
// ---------------------------------------------------------------------------
#define BM 128
#define BN 128
#define BK 32
#define TP 36                                  /* tile pitch (floats) */
#define TSZ (128 * TP)                         /* one tile (floats)   */
#define GEMM_SMEM ((4 * TSZ) * (int)sizeof(float))   /* 73728 B */

template <bool ROUND_OUT>
__global__ __launch_bounds__(256, 2) void gemm_tf32_kernel(
    const float* __restrict__ A, const float* __restrict__ Wt,
    const float* __restrict__ bias, float* __restrict__ C,
    int M, int N, int K)
{
    extern __shared__ float dyn[];
    float* As = dyn;               // [2][128][TP]
    float* Bs = dyn + 2 * TSZ;     // [2][128][TP]  (rows = n)

    const int tid  = threadIdx.x;
    const int lane = tid & 31;
    const int warp = tid >> 5;
    const int wr   = warp >> 2;          // 0..1
    const int wc   = warp & 3;           // 0..3

    const int m0 = blockIdx.y * BM;
    const int n0 = blockIdx.x * BN;

    const int lrow = tid >> 3;           // 0..31 (rows lrow + 32*i)
    const int lcol = (tid & 7) * 4;      // k offset within BK

    const int T = K / BK;

    auto loadtile = [&](int t) {
        float* as = As + (t & 1) * TSZ;
        float* bs = Bs + (t & 1) * TSZ;
        const int k0 = t * BK;
#pragma unroll
        for (int i = 0; i < 4; ++i)
            cp16(&as[(lrow + 32 * i) * TP + lcol],
                 A + (size_t)(m0 + lrow + 32 * i) * K + k0 + lcol);
#pragma unroll
        for (int i = 0; i < 4; ++i)
            cp16(&bs[(lrow + 32 * i) * TP + lcol],
                 Wt + (size_t)(n0 + lrow + 32 * i) * K + k0 + lcol);
        CP_COMMIT();
    };

    float acc[4][4][4];
#pragma unroll
    for (int mi = 0; mi < 4; ++mi)
#pragma unroll
        for (int nj = 0; nj < 4; ++nj)
#pragma unroll
            for (int r = 0; r < 4; ++r) acc[mi][nj][r] = 0.f;

    // LDSM lane->row/k mapping (same for A and B tiles)
    const int sm_row = lane & 15;                 // row within 16-row frag (A)
    const int sm_k4  = (lane & 16) ? 4 : 0;       // A: k-half from lane bit4
    const int b_row  = ((lane & 16) ? 8 : 0) + (lane & 7);  // B: row within 16
    const int b_k4   = (lane & 8) ? 4 : 0;        // B: k-half from lane bit3

    loadtile(0);

    for (int t = 0; t < T; ++t) {
        CP_WAIT(0);
        __syncthreads();
        if (t + 1 < T) loadtile(t + 1);

        const float* as = As + (t & 1) * TSZ;
        const float* bs = Bs + (t & 1) * TSZ;

#pragma unroll
        for (int ks = 0; ks < 4; ++ks) {
            unsigned af[4][4], bq[2][4];
            const float* ab = as + (wr * 64 + sm_row) * TP + ks * 8 + sm_k4;
            const float* bb = bs + (wc * 32 + b_row) * TP + ks * 8 + b_k4;
#pragma unroll
            for (int mi = 0; mi < 4; ++mi)
                ldsm_x4(af[mi], ab + mi * 16 * TP);
#pragma unroll
            for (int p = 0; p < 2; ++p)
                ldsm_x4(bq[p], bb + p * 16 * TP);   // r0,r1 = nj=2p; r2,r3 = nj=2p+1
#pragma unroll
            for (int mi = 0; mi < 4; ++mi)
#pragma unroll
                for (int p = 0; p < 2; ++p) {
                    mma_tf32(acc[mi][2 * p],     af[mi], &bq[p][0]);
                    mma_tf32(acc[mi][2 * p + 1], af[mi], &bq[p][2]);
                }
        }
    }

    // epilogue: bias + store
    const int grp = lane >> 2;
    const int qid = lane & 3;
#pragma unroll
    for (int mi = 0; mi < 4; ++mi) {
#pragma unroll
        for (int nj = 0; nj < 4; ++nj) {
            const int row = m0 + wr * 64 + mi * 16 + grp;
            const int col = n0 + wc * 32 + nj * 8 + 2 * qid;
            const float b0 = bias[col];
            const float b1 = bias[col + 1];
            float c00 = acc[mi][nj][0] + b0, c01 = acc[mi][nj][1] + b1;
            float c10 = acc[mi][nj][2] + b0, c11 = acc[mi][nj][3] + b1;
            if (ROUND_OUT) {
                c00 = tf32r(c00); c01 = tf32r(c01);
                c10 = tf32r(c10); c11 = tf32r(c11);
            }
            *(float2*)&C[(size_t)row * N + col] = make_float2(c00, c01);
            *(float2*)&C[(size_t)(row + 8) * N + col] = make_float2(c10, c11);
        }
    }
}

// ---------------------------------------------------------------------------
// Flash attention (causal), tf32. qkv pre-rounded. LDSM for K (S-phase B) and
// P (PV-phase A); V scalar. 69KB smem, 3 CTAs/SM. Grid: (S/64, B*H), 128 thr.
// ---------------------------------------------------------------------------
#define QP 68   /* pitch for Qs/Ks/Ps */
#define VP 72   /* pitch for Vs */
#define FLASH_SMEM ((3 * 64 * QP + 64 * VP) * (int)sizeof(float))  /* 70656 B */

__global__ __launch_bounds__(128) void flash_tf32_kernel(
    const float* __restrict__ qkv, float* __restrict__ out)
{
    extern __shared__ float smf[];
    float* Qs = smf;               // 64*QP
    float* Ks = Qs + 64 * QP;      // 64*QP
    float* Ps = Ks + 64 * QP;      // 64*QP
    float* Vs = Ps + 64 * QP;      // 64*VP

    const int tid  = threadIdx.x;
    const int lane = tid & 31;
    const int warp = tid >> 5;     // 0..3, 16 queries each
    const int grp  = lane >> 2;
    const int qid  = lane & 3;

    const int bh = blockIdx.y;
    const int b  = bh / HEADS;
    const int h  = bh % HEADS;
    const int qt = gridDim.x - 1 - blockIdx.x;   // heavy tiles first
    const int q0 = qt * 64;
    const float scale = 0.125f;

    const float* qbase = qkv + (size_t)(b * SEQ) * NQKV + h * HDIM;
    const float* kbase = qbase + DIM;
    const float* vbase = qbase + 2 * DIM;

    const int lr = tid >> 4;            // 0..7
    const int lc = (tid & 15) * 4;      // 0..60

    // Load Q tile (pre-rounded)
#pragma unroll
    for (int i = 0; i < 8; ++i) {
        float4 v = *(const float4*)(qbase + (size_t)(q0 + lr + 8 * i) * NQKV + lc);
        *(float4*)&Qs[(lr + 8 * i) * QP + lc] = v;
    }
    __syncthreads();

    // Q fragments register-resident (LDSM A-frags)
    const int a_row = lane & 15;
    const int a_k4  = (lane & 16) ? 4 : 0;
    unsigned qf[8][4];
#pragma unroll
    for (int ks = 0; ks < 8; ++ks)
        ldsm_x4(qf[ks], &Qs[(warp * 16 + a_row) * QP + ks * 8 + a_k4]);

    float m0r = -INFINITY, m1r = -INFINITY, l0 = 0.f, l1 = 0.f;
    float o[8][4];
#pragma unroll
    for (int j = 0; j < 8; ++j)
#pragma unroll
        for (int r = 0; r < 4; ++r) o[j][r] = 0.f;

    // K LDSM B-frag mapping: x4 covers j-pair (2jj, 2jj+1)
    const int k_rowi = ((lane & 16) ? 8 : 0) + (lane & 7);   // row within 16-kv pair
    const int k_k4   = (lane & 8) ? 4 : 0;

    const int ntiles = qt + 1;
    for (int t = 0; t < ntiles; ++t) {
        const int k0 = t * 64;
        __syncthreads();
#pragma unroll
        for (int i = 0; i < 8; ++i) {
            const int row = lr + 8 * i;
            float4 kv = *(const float4*)(kbase + (size_t)(k0 + row) * NQKV + lc);
            float4 vv = *(const float4*)(vbase + (size_t)(k0 + row) * NQKV + lc);
            *(float4*)&Ks[row * QP + lc] = kv;
            *(float4*)&Vs[row * VP + lc] = vv;
        }
        __syncthreads();

        // S = Q K^T  (warp tile 16x64): ks outer, j-pairs via LDSM.x4
        float s[8][4];
#pragma unroll
        for (int j = 0; j < 8; ++j)
            s[j][0] = s[j][1] = s[j][2] = s[j][3] = 0.f;
#pragma unroll
        for (int ks = 0; ks < 8; ++ks) {
#pragma unroll
            for (int jj = 0; jj < 4; ++jj) {
                unsigned kq[4];
                ldsm_x4(kq, &Ks[(jj * 16 + k_rowi) * QP + ks * 8 + k_k4]);
                mma_tf32(s[2 * jj],     qf[ks], &kq[0]);
                mma_tf32(s[2 * jj + 1], qf[ks], &kq[2]);
            }
        }

        // scale + causal mask (diag tile only)
        const bool diag = (t == ntiles - 1);
        const int qi0 = q0 + warp * 16 + grp;
#pragma unroll
        for (int j = 0; j < 8; ++j) {
#pragma unroll
            for (int r = 0; r < 4; ++r) {
                float v = s[j][r] * scale;
                if (diag) {
                    const int kj = k0 + j * 8 + 2 * qid + (r & 1);
                    const int qi = qi0 + ((r >= 2) ? 8 : 0);
                    if (kj > qi) v = -INFINITY;
                }
                s[j][r] = v;
            }
        }

        // online softmax (rows grp and grp+8)
        float mx0 = -INFINITY, mx1 = -INFINITY;
#pragma unroll
        for (int j = 0; j < 8; ++j) {
            mx0 = fmaxf(mx0, fmaxf(s[j][0], s[j][1]));
            mx1 = fmaxf(mx1, fmaxf(s[j][2], s[j][3]));
        }
        mx0 = fmaxf(mx0, __shfl_xor_sync(0xffffffffu, mx0, 1));
        mx0 = fmaxf(mx0, __shfl_xor_sync(0xffffffffu, mx0, 2));
        mx1 = fmaxf(mx1, __shfl_xor_sync(0xffffffffu, mx1, 1));
        mx1 = fmaxf(mx1, __shfl_xor_sync(0xffffffffu, mx1, 2));

        const float nm0 = fmaxf(m0r, mx0);
        const float nm1 = fmaxf(m1r, mx1);
        const float corr0 = __expf(m0r - nm0);
        const float corr1 = __expf(m1r - nm1);
        m0r = nm0; m1r = nm1;

        float sum0 = 0.f, sum1 = 0.f;
#pragma unroll
        for (int j = 0; j < 8; ++j) {
            s[j][0] = __expf(s[j][0] - nm0);
            s[j][1] = __expf(s[j][1] - nm0);
            s[j][2] = __expf(s[j][2] - nm1);
            s[j][3] = __expf(s[j][3] - nm1);
            sum0 += s[j][0] + s[j][1];
            sum1 += s[j][2] + s[j][3];
        }
        sum0 += __shfl_xor_sync(0xffffffffu, sum0, 1);
        sum0 += __shfl_xor_sync(0xffffffffu, sum0, 2);
        sum1 += __shfl_xor_sync(0xffffffffu, sum1, 1);
        sum1 += __shfl_xor_sync(0xffffffffu, sum1, 2);
        l0 = l0 * corr0 + sum0;
        l1 = l1 * corr1 + sum1;
#pragma unroll
        for (int j = 0; j < 8; ++j) {
            o[j][0] *= corr0; o[j][1] *= corr0;
            o[j][2] *= corr1; o[j][3] *= corr1;
        }

        // P fragments -> smem (C-layout -> A-layout), warp-private
#pragma unroll
        for (int j = 0; j < 8; ++j) {
            float* p0 = &Ps[(warp * 16 + grp) * QP + j * 8 + 2 * qid];
            float* p1 = &Ps[(warp * 16 + grp + 8) * QP + j * 8 + 2 * qid];
            *(float2*)p0 = make_float2(tf32r(s[j][0]), tf32r(s[j][1]));
            *(float2*)p1 = make_float2(tf32r(s[j][2]), tf32r(s[j][3]));
        }
        __syncwarp();

        // O += P @ V  (P via LDSM, V scalar)
#pragma unroll
        for (int ks = 0; ks < 8; ++ks) {
            unsigned pf[4];
            ldsm_x4(pf, &Ps[(warp * 16 + a_row) * QP + ks * 8 + a_k4]);
#pragma unroll
            for (int j = 0; j < 8; ++j) {
                const float* bbase = &Vs[(ks * 8 + qid) * VP + j * 8 + grp];
                unsigned bf[2];
                bf[0] = __float_as_uint(bbase[0]);
                bf[1] = __float_as_uint(bbase[4 * VP]);
                mma_tf32(o[j], pf, bf);
            }
        }
    }

    // write normalized output (tf32-rounded: feeds out-proj MMA directly)
    const float inv0 = 1.0f / l0;
    const float inv1 = 1.0f / l1;
    const int row0 = q0 + warp * 16 + grp;
#pragma unroll
    for (int j = 0; j < 8; ++j) {
        const int col = h * HDIM + j * 8 + 2 * qid;
        *(float2*)&out[((size_t)(b * SEQ) + row0) * DIM + col] =
            make_float2(tf32r(o[j][0] * inv0), tf32r(o[j][1] * inv0));
        *(float2*)&out[((size_t)(b * SEQ) + row0 + 8) * DIM + col] =
            make_float2(tf32r(o[j][2] * inv1), tf32r(o[j][3] * inv1));
    }
}

// ---------------------------------------------------------------------------
extern "C" void kernel_launch(void* const* d_in, const int* in_sizes, int n_in,
                              void* d_out, int out_size)
{
    const float* x      = (const float*)d_in[0];   // [B,S,D]
    const float* qkv_w  = (const float*)d_in[1];   // [D, 3D]
    const float* qkv_b  = (const float*)d_in[2];   // [3D]
    const float* out_w  = (const float*)d_in[3];   // [D, D]
    const float* out_b  = (const float*)d_in[4];   // [D]
    float* out = (float*)d_out;

    float *qkv_buf, *att_buf, *wrs;
    cudaGetSymbolAddress((void**)&qkv_buf, g_qkv);
    cudaGetSymbolAddress((void**)&att_buf, g_att);
    cudaGetSymbolAddress((void**)&wrs, g_wrs);

    // xr aliases att_buf (dead before flash writes att); weights transposed+rounded.
    float* xr    = att_buf;
    float* wr_t  = wrs;                                  // [NQKV][DIM]
    float* owr_t = wrs + (size_t)DIM * NQKV;             // [DIM][DIM]

    cudaFuncSetAttribute(gemm_tf32_kernel<true>,
                         cudaFuncAttributeMaxDynamicSharedMemorySize, GEMM_SMEM);
    cudaFuncSetAttribute(gemm_tf32_kernel<false>,
                         cudaFuncAttributeMaxDynamicSharedMemorySize, GEMM_SMEM);
    cudaFuncSetAttribute(flash_tf32_kernel,
                         cudaFuncAttributeMaxDynamicSharedMemorySize, FLASH_SMEM);

    // 0) prep: round x; round+transpose both weight matrices
    {
        int n4 = MROWS * DIM / 4;
        round_tf32_kernel<<<(n4 + 255) / 256, 256>>>(x, xr, n4);
        dim3 g1(NQKV / 32, DIM / 32);
        round_transpose_kernel<<<g1, 256>>>(qkv_w, wr_t, DIM, NQKV);
        dim3 g2(DIM / 32, DIM / 32);
        round_transpose_kernel<<<g2, 256>>>(out_w, owr_t, DIM, DIM);
    }
    // 1) QKV projection (rounded output)
    {
        dim3 grid(NQKV / BN, MROWS / BM);
        gemm_tf32_kernel<true><<<grid, 256, GEMM_SMEM>>>(xr, wr_t, qkv_b, qkv_buf,
                                                         MROWS, NQKV, DIM);
    }
    // 2) Causal flash attention (overwrites xr with att)
    {
        dim3 grid(SEQ / 64, BATCH * HEADS);
        flash_tf32_kernel<<<grid, 128, FLASH_SMEM>>>(qkv_buf, att_buf);
    }
    // 3) Output projection (exact fp32 out)
    {
        dim3 grid(DIM / BN, MROWS / BM);
        gemm_tf32_kernel<false><<<grid, 256, GEMM_SMEM>>>(att_buf, owr_t, out_b, out,
                                                          MROWS, DIM, DIM);
    }
}